// round 4
// baseline (speedup 1.0000x reference)
#include <cuda_runtime.h>
#include <cuda_bf16.h>
#include <cstdint>

// Problem constants
#define BATCH 2
#define SEQ   2048
#define DMODEL 1024
#define NHEAD 16
#define HDIM  64
#define MROWS (BATCH * SEQ)          // 4096
#define LN_EPS 1e-5f

// ---------------- scratch (no allocations allowed; use device globals) ------
// NOTE: these symbols are referenced ONLY from device code. Passing them as
// host-side kernel arguments silently binds the host shadow address (which on
// GB300 is even writable via ATS) — that was the round-2/3 bug.
__device__ float g_h[(size_t)MROWS * DMODEL];     // layernorm output  [B*S, D]
__device__ float g_q[(size_t)MROWS * DMODEL];     // [B,H,S,hd]
__device__ float g_k[(size_t)MROWS * DMODEL];     // [B,H,S,hd]
__device__ float g_v[(size_t)MROWS * DMODEL];     // [B,H,S,hd]
__device__ float g_attn[(size_t)MROWS * DMODEL];  // [B,S,D]
__device__ int   g_mask_allones;

// ---------------- layernorm --------------------------------------------------
__global__ __launch_bounds__(256) void ln_kernel(const float* __restrict__ x,
                                                 const float* __restrict__ gamma,
                                                 const float* __restrict__ beta) {
    int row = blockIdx.x;
    const float* xr = x + (size_t)row * DMODEL;
    float v[4];
    float s = 0.f, sq = 0.f;
#pragma unroll
    for (int i = 0; i < 4; i++) {
        v[i] = xr[threadIdx.x + 256 * i];
        s += v[i];
        sq += v[i] * v[i];
    }
#pragma unroll
    for (int o = 16; o; o >>= 1) {
        s  += __shfl_xor_sync(0xffffffffu, s, o);
        sq += __shfl_xor_sync(0xffffffffu, sq, o);
    }
    __shared__ float ss[8], ssq[8];
    int w = threadIdx.x >> 5, l = threadIdx.x & 31;
    if (l == 0) { ss[w] = s; ssq[w] = sq; }
    __syncthreads();
    if (w == 0) {
        s  = (l < 8) ? ss[l]  : 0.f;
        sq = (l < 8) ? ssq[l] : 0.f;
#pragma unroll
        for (int o = 4; o; o >>= 1) {
            s  += __shfl_xor_sync(0xffffffffu, s, o);
            sq += __shfl_xor_sync(0xffffffffu, sq, o);
        }
        if (l == 0) { ss[0] = s; ssq[0] = sq; }
    }
    __syncthreads();
    float mu  = ss[0] * (1.f / DMODEL);
    float var = ssq[0] * (1.f / DMODEL) - mu * mu;
    float inv = rsqrtf(var + LN_EPS);
    float* hr = g_h + (size_t)row * DMODEL;
#pragma unroll
    for (int i = 0; i < 4; i++) {
        int c = threadIdx.x + 256 * i;
        hr[c] = (v[i] - mu) * inv * gamma[c] + beta[c];
    }
}

// ---------------- mask all-ones scan -----------------------------------------
__global__ void mask_init_kernel() { g_mask_allones = 1; }

__global__ void mask_scan_kernel(const int4* __restrict__ m4, int n4) {
    int ok = 1;
    for (int i = blockIdx.x * blockDim.x + threadIdx.x; i < n4;
         i += gridDim.x * blockDim.x) {
        int4 t = m4[i];
        ok &= (t.x != 0) & (t.y != 0) & (t.z != 0) & (t.w != 0);
    }
    if (!ok) atomicAnd(&g_mask_allones, 0);
}

// ---------------- QKV fused SGEMM: C = h @ W^T + b, reordered to [B,H,S,hd] --
// BM=BN=128, BK=8, 256 threads, 8x8 per thread.
__global__ __launch_bounds__(256) void gemm_qkv_kernel(
    const float* __restrict__ Wq, const float* __restrict__ bq,
    const float* __restrict__ Wk, const float* __restrict__ bk,
    const float* __restrict__ Wv, const float* __restrict__ bv) {
    const float* W;
    const float* bias;
    float* C;
    if (blockIdx.z == 0)      { W = Wq; bias = bq; C = g_q; }
    else if (blockIdx.z == 1) { W = Wk; bias = bk; C = g_k; }
    else                      { W = Wv; bias = bv; C = g_v; }

    __shared__ float As[8][128];
    __shared__ float Bs[8][128];

    int tid = threadIdx.x;
    int tx = tid & 15, ty = tid >> 4;
    int rowBase = blockIdx.y * 128;
    int colBase = blockIdx.x * 128;
    int lr = tid >> 1;
    int lc = (tid & 1) * 4;

    float acc[8][8];
#pragma unroll
    for (int i = 0; i < 8; i++)
#pragma unroll
        for (int j = 0; j < 8; j++) acc[i][j] = 0.f;

    const float* aptr = g_h + (size_t)(rowBase + lr) * DMODEL + lc;
    const float* bptr = W   + (size_t)(colBase + lr) * DMODEL + lc;

    for (int k0 = 0; k0 < DMODEL; k0 += 8) {
        float4 a4 = *(const float4*)(aptr + k0);
        float4 b4 = *(const float4*)(bptr + k0);
        __syncthreads();
        As[lc + 0][lr] = a4.x; As[lc + 1][lr] = a4.y;
        As[lc + 2][lr] = a4.z; As[lc + 3][lr] = a4.w;
        Bs[lc + 0][lr] = b4.x; Bs[lc + 1][lr] = b4.y;
        Bs[lc + 2][lr] = b4.z; Bs[lc + 3][lr] = b4.w;
        __syncthreads();
#pragma unroll
        for (int k = 0; k < 8; k++) {
            float a[8], b[8];
            *(float4*)(a)     = *(const float4*)&As[k][ty * 8];
            *(float4*)(a + 4) = *(const float4*)&As[k][ty * 8 + 4];
            *(float4*)(b)     = *(const float4*)&Bs[k][tx * 8];
            *(float4*)(b + 4) = *(const float4*)&Bs[k][tx * 8 + 4];
#pragma unroll
            for (int i = 0; i < 8; i++)
#pragma unroll
                for (int j = 0; j < 8; j++) acc[i][j] = fmaf(a[i], b[j], acc[i][j]);
        }
    }

    // epilogue: write reordered [B,H,S,hd]
#pragma unroll
    for (int i = 0; i < 8; i++) {
        int m = rowBase + ty * 8 + i;
        int bb = m >> 11;            // /SEQ
        int srow = m & 2047;
#pragma unroll
        for (int j = 0; j < 8; j++) {
            int n = colBase + tx * 8 + j;
            int hh = n >> 6;
            int d  = n & 63;
            C[(((size_t)(bb * NHEAD + hh) * SEQ + srow) << 6) + d] = acc[i][j] + bias[n];
        }
    }
}

// ---------------- flash attention (fp32, online softmax, static smem) --------
// BM=BN=64, hd=64. 256 threads; 16x16 grid of 4x4 microtiles.
// Static smem: Qt (Q transposed), KP union (K transposed, then P transposed),
// Vs (natural). 3 * 64*64 * 4B = 49152 B = 48 KB -> no opt-in needed.
// Output goes to g_attn via device-side symbol reference (NOT a host-passed
// pointer).
__global__ __launch_bounds__(256) void attn_kernel(const int* __restrict__ mask) {
    __shared__ float Qt[64 * 64];    // Qt[d*64 + r]  = Q[r][d]
    __shared__ float KP[64 * 64];    // Kt[d*64 + c]  = K[c][d]; later Pt[c*64 + r]
    __shared__ float Vs[64 * 64];    // Vs[c*64 + d]  = V[c][d]

    int tid = threadIdx.x;
    int tx = tid & 15, ty = tid >> 4;
    int qt = blockIdx.x, hh = blockIdx.y, bb = blockIdx.z;

    size_t headOff = ((size_t)(bb * NHEAD + hh)) * SEQ * HDIM;
    const float* qb = g_q + headOff + (size_t)qt * 64 * HDIM;
    const float* kb = g_k + headOff;
    const float* vb = g_v + headOff;

    // load Q transposed: thread handles (row r, d-chunk dc)
#pragma unroll
    for (int p = 0; p < 4; p++) {
        int idx = tid + p * 256;          // 0..1023
        int r  = idx & 63;
        int dc = idx >> 6;                // 0..15
        float4 f = *(const float4*)(qb + r * HDIM + dc * 4);
        Qt[(dc * 4 + 0) * 64 + r] = f.x;
        Qt[(dc * 4 + 1) * 64 + r] = f.y;
        Qt[(dc * 4 + 2) * 64 + r] = f.z;
        Qt[(dc * 4 + 3) * 64 + r] = f.w;
    }

    float acc[4][4];
    float m_r[4], l_r[4];
#pragma unroll
    for (int i = 0; i < 4; i++) {
        m_r[i] = -1e30f;
        l_r[i] = 0.f;
#pragma unroll
        for (int j = 0; j < 4; j++) acc[i][j] = 0.f;
    }

    bool use_mask = (g_mask_allones == 0);

    for (int kt = 0; kt < SEQ / 64; kt++) {
        __syncthreads();   // prev iteration's P/V readers done before overwrite
        const float* kbt = kb + (size_t)kt * 64 * HDIM;
        const float* vbt = vb + (size_t)kt * 64 * HDIM;
        // K transposed
#pragma unroll
        for (int p = 0; p < 4; p++) {
            int idx = tid + p * 256;
            int c  = idx & 63;
            int dc = idx >> 6;
            float4 f = *(const float4*)(kbt + c * HDIM + dc * 4);
            KP[(dc * 4 + 0) * 64 + c] = f.x;
            KP[(dc * 4 + 1) * 64 + c] = f.y;
            KP[(dc * 4 + 2) * 64 + c] = f.z;
            KP[(dc * 4 + 3) * 64 + c] = f.w;
        }
        // V natural
#pragma unroll
        for (int p = 0; p < 4; p++) {
            int idx = tid + p * 256;
            int c  = idx >> 4;
            int d4 = (idx & 15) << 2;
            *(float4*)&Vs[c * 64 + d4] = *(const float4*)(vbt + c * HDIM + d4);
        }
        __syncthreads();

        // GEMM1: sc = Q @ K^T  (both operands transposed in smem -> float4 loads)
        float sc[4][4];
#pragma unroll
        for (int i = 0; i < 4; i++)
#pragma unroll
            for (int j = 0; j < 4; j++) sc[i][j] = 0.f;
#pragma unroll 16
        for (int d = 0; d < HDIM; d++) {
            float4 a4 = *(const float4*)&Qt[d * 64 + ty * 4];
            float4 b4 = *(const float4*)&KP[d * 64 + tx * 4];
            float a[4] = {a4.x, a4.y, a4.z, a4.w};
            float b[4] = {b4.x, b4.y, b4.z, b4.w};
#pragma unroll
            for (int i = 0; i < 4; i++)
#pragma unroll
                for (int j = 0; j < 4; j++) sc[i][j] = fmaf(a[i], b[j], sc[i][j]);
        }

        // scale + (rare) mask
#pragma unroll
        for (int i = 0; i < 4; i++)
#pragma unroll
            for (int j = 0; j < 4; j++) sc[i][j] *= 0.125f;   // 1/sqrt(64)
        if (use_mask) {
#pragma unroll
            for (int i = 0; i < 4; i++) {
                int qAbs = qt * 64 + ty * 4 + i;
#pragma unroll
                for (int j = 0; j < 4; j++) {
                    int kAbs = kt * 64 + tx * 4 + j;
                    if (mask[((size_t)bb * SEQ + qAbs) * SEQ + kAbs] == 0)
                        sc[i][j] = -1e30f;
                }
            }
        }

        // register online softmax; row group = 16 consecutive lanes (same ty)
#pragma unroll
        for (int i = 0; i < 4; i++) {
            float tmax = fmaxf(fmaxf(sc[i][0], sc[i][1]), fmaxf(sc[i][2], sc[i][3]));
#pragma unroll
            for (int o = 1; o < 16; o <<= 1)
                tmax = fmaxf(tmax, __shfl_xor_sync(0xffffffffu, tmax, o));
            float mnew = fmaxf(m_r[i], tmax);
            float corr = __expf(m_r[i] - mnew);
            float rsum = 0.f;
#pragma unroll
            for (int j = 0; j < 4; j++) {
                sc[i][j] = __expf(sc[i][j] - mnew);
                rsum += sc[i][j];
            }
#pragma unroll
            for (int o = 1; o < 16; o <<= 1)
                rsum += __shfl_xor_sync(0xffffffffu, rsum, o);
            l_r[i] = l_r[i] * corr + rsum;
            m_r[i] = mnew;
#pragma unroll
            for (int j = 0; j < 4; j++) acc[i][j] *= corr;
        }

        __syncthreads();   // all K reads done -> safe to overwrite KP with P
        // store P transposed: Pt[c*64 + r], float4 over r
#pragma unroll
        for (int j = 0; j < 4; j++) {
            float4 v;
            v.x = sc[0][j]; v.y = sc[1][j]; v.z = sc[2][j]; v.w = sc[3][j];
            *(float4*)&KP[(tx * 4 + j) * 64 + ty * 4] = v;
        }
        __syncthreads();

        // PV: acc += P @ V   (Pt + Vs -> float4 loads)
#pragma unroll 16
        for (int kk = 0; kk < 64; kk++) {
            float4 a4 = *(const float4*)&KP[kk * 64 + ty * 4];
            float4 b4 = *(const float4*)&Vs[kk * 64 + tx * 4];
            float a[4] = {a4.x, a4.y, a4.z, a4.w};
            float b[4] = {b4.x, b4.y, b4.z, b4.w};
#pragma unroll
            for (int i = 0; i < 4; i++)
#pragma unroll
                for (int j = 0; j < 4; j++) acc[i][j] = fmaf(a[i], b[j], acc[i][j]);
        }
    }

    // final normalize + write [B,S,D] into device-global g_attn
#pragma unroll
    for (int i = 0; i < 4; i++) {
        float inv = 1.f / l_r[i];
        int sAbs = qt * 64 + ty * 4 + i;
        float4 o;
        o.x = acc[i][0] * inv;
        o.y = acc[i][1] * inv;
        o.z = acc[i][2] * inv;
        o.w = acc[i][3] * inv;
        *(float4*)&g_attn[((size_t)(bb * SEQ + sAbs)) * DMODEL + hh * HDIM + tx * 4] = o;
    }
}

// ---------------- out projection: out = attn @ Wo^T + bo + residual ----------
__global__ __launch_bounds__(256) void gemm_out_kernel(const float* __restrict__ W,
                                                       const float* __restrict__ bias,
                                                       const float* __restrict__ resid,
                                                       float* __restrict__ outp) {
    __shared__ float As[8][128];
    __shared__ float Bs[8][128];

    int tid = threadIdx.x;
    int tx = tid & 15, ty = tid >> 4;
    int rowBase = blockIdx.y * 128;
    int colBase = blockIdx.x * 128;
    int lr = tid >> 1;
    int lc = (tid & 1) * 4;

    float acc[8][8];
#pragma unroll
    for (int i = 0; i < 8; i++)
#pragma unroll
        for (int j = 0; j < 8; j++) acc[i][j] = 0.f;

    const float* aptr = g_attn + (size_t)(rowBase + lr) * DMODEL + lc;
    const float* bptr = W      + (size_t)(colBase + lr) * DMODEL + lc;

    for (int k0 = 0; k0 < DMODEL; k0 += 8) {
        float4 a4 = *(const float4*)(aptr + k0);
        float4 b4 = *(const float4*)(bptr + k0);
        __syncthreads();
        As[lc + 0][lr] = a4.x; As[lc + 1][lr] = a4.y;
        As[lc + 2][lr] = a4.z; As[lc + 3][lr] = a4.w;
        Bs[lc + 0][lr] = b4.x; Bs[lc + 1][lr] = b4.y;
        Bs[lc + 2][lr] = b4.z; Bs[lc + 3][lr] = b4.w;
        __syncthreads();
#pragma unroll
        for (int k = 0; k < 8; k++) {
            float a[8], b[8];
            *(float4*)(a)     = *(const float4*)&As[k][ty * 8];
            *(float4*)(a + 4) = *(const float4*)&As[k][ty * 8 + 4];
            *(float4*)(b)     = *(const float4*)&Bs[k][tx * 8];
            *(float4*)(b + 4) = *(const float4*)&Bs[k][tx * 8 + 4];
#pragma unroll
            for (int i = 0; i < 8; i++)
#pragma unroll
                for (int j = 0; j < 8; j++) acc[i][j] = fmaf(a[i], b[j], acc[i][j]);
        }
    }

#pragma unroll
    for (int i = 0; i < 8; i++) {
        int m = rowBase + ty * 8 + i;
#pragma unroll
        for (int j = 0; j < 8; j++) {
            int n = colBase + tx * 8 + j;
            size_t idx = (size_t)m * DMODEL + n;
            outp[idx] = acc[i][j] + bias[n] + resid[idx];
        }
    }
}

// ---------------- launcher ----------------------------------------------------
extern "C" void kernel_launch(void* const* d_in, const int* in_sizes, int n_in,
                              void* d_out, int out_size) {
    const float* x     = (const float*)d_in[0];
    const int*   mask  = (const int*)d_in[1];
    const float* Wq    = (const float*)d_in[2];
    const float* bq    = (const float*)d_in[3];
    const float* Wk    = (const float*)d_in[4];
    const float* bk    = (const float*)d_in[5];
    const float* Wv    = (const float*)d_in[6];
    const float* bv    = (const float*)d_in[7];
    const float* Wo    = (const float*)d_in[8];
    const float* bo    = (const float*)d_in[9];
    const float* gamma = (const float*)d_in[10];
    const float* beta  = (const float*)d_in[11];
    float* outp = (float*)d_out;

    // layernorm
    ln_kernel<<<MROWS, 256>>>(x, gamma, beta);

    // mask all-ones scan (lets attention skip mask loads deterministically)
    mask_init_kernel<<<1, 1>>>();
    {
        int n4 = (BATCH * SEQ * SEQ) / 4;
        mask_scan_kernel<<<256, 256>>>((const int4*)mask, n4);
    }

    // QKV projections (z selects q/k/v)
    {
        dim3 grid(DMODEL / 128, MROWS / 128, 3);
        gemm_qkv_kernel<<<grid, 256>>>(Wq, bq, Wk, bk, Wv, bv);
    }

    // flash attention (static 48KB smem; writes g_attn device-side)
    {
        dim3 grid(SEQ / 64, NHEAD, BATCH);
        attn_kernel<<<grid, 256>>>(mask);
    }

    // output projection + bias + residual
    {
        dim3 grid(DMODEL / 128, MROWS / 128);
        gemm_out_kernel<<<grid, 256>>>(Wo, bo, x, outp);
    }
}

// round 5
// speedup vs baseline: 7.1560x; 7.1560x over previous
#include <cuda_runtime.h>
#include <cuda_bf16.h>
#include <cstdint>

#define BATCH 2
#define SEQ   2048
#define DMODEL 1024
#define NHEAD 16
#define HDIM  64
#define MROWS (BATCH * SEQ)
#define LN_EPS 1e-5f

typedef __nv_bfloat16 bf16;

// ---------------- device-global scratch (referenced ONLY from device code) ---
__device__ bf16 g_hb[(size_t)MROWS * DMODEL];     // LN output, bf16
__device__ bf16 g_Wqb[DMODEL * DMODEL];
__device__ bf16 g_Wkb[DMODEL * DMODEL];
__device__ bf16 g_Wvb[DMODEL * DMODEL];
__device__ bf16 g_Wob[DMODEL * DMODEL];
__device__ bf16 g_qb[(size_t)MROWS * DMODEL];     // [B,H,S,hd]
__device__ bf16 g_kb[(size_t)MROWS * DMODEL];
__device__ bf16 g_vb[(size_t)MROWS * DMODEL];
__device__ bf16 g_attnb[(size_t)MROWS * DMODEL];  // [B*S, D]
__device__ int  g_mask_allones;

// ---------------- PTX helpers -------------------------------------------------
__device__ __forceinline__ uint32_t s2u(const void* p) {
    return (uint32_t)__cvta_generic_to_shared(p);
}
__device__ __forceinline__ void cp16(uint32_t saddr, const void* g) {
    asm volatile("cp.async.cg.shared.global [%0], [%1], 16;\n" :: "r"(saddr), "l"(g));
}
__device__ __forceinline__ void cp_commit() { asm volatile("cp.async.commit_group;\n"); }
__device__ __forceinline__ void cp_wait0()  { asm volatile("cp.async.wait_group 0;\n"); }

__device__ __forceinline__ void ldsm4(uint32_t r[4], uint32_t addr) {
    asm volatile("ldmatrix.sync.aligned.m8n8.x4.shared.b16 {%0,%1,%2,%3}, [%4];\n"
                 : "=r"(r[0]), "=r"(r[1]), "=r"(r[2]), "=r"(r[3]) : "r"(addr));
}
__device__ __forceinline__ void ldsm4t(uint32_t r[4], uint32_t addr) {
    asm volatile("ldmatrix.sync.aligned.m8n8.x4.trans.shared.b16 {%0,%1,%2,%3}, [%4];\n"
                 : "=r"(r[0]), "=r"(r[1]), "=r"(r[2]), "=r"(r[3]) : "r"(addr));
}
__device__ __forceinline__ void mma16816(float c[4], const uint32_t a[4], const uint32_t b[2]) {
    asm volatile(
        "mma.sync.aligned.m16n8k16.row.col.f32.bf16.bf16.f32 "
        "{%0,%1,%2,%3}, {%4,%5,%6,%7}, {%8,%9}, {%0,%1,%2,%3};\n"
        : "+f"(c[0]), "+f"(c[1]), "+f"(c[2]), "+f"(c[3])
        : "r"(a[0]), "r"(a[1]), "r"(a[2]), "r"(a[3]), "r"(b[0]), "r"(b[1]));
}
__device__ __forceinline__ uint32_t pack_bf2(float lo, float hi) {
    __nv_bfloat162 h = __floats2bfloat162_rn(lo, hi);
    return *reinterpret_cast<uint32_t*>(&h);
}
// swizzles: byte offset within a tile whose rows are 64B / 128B
__device__ __forceinline__ int sw64(int row, int c16)  { return (row << 6) + ((c16 ^ ((row >> 1) & 3)) << 4); }
__device__ __forceinline__ int sw128(int row, int c16) { return (row << 7) + ((c16 ^ (row & 7)) << 4); }

// ---------------- layernorm -> bf16 ------------------------------------------
__global__ __launch_bounds__(256) void ln_kernel(const float* __restrict__ x,
                                                 const float* __restrict__ gamma,
                                                 const float* __restrict__ beta) {
    int row = blockIdx.x;
    const float* xr = x + (size_t)row * DMODEL;
    int c0 = threadIdx.x * 4;
    float4 f = *(const float4*)(xr + c0);
    float s  = f.x + f.y + f.z + f.w;
    float sq = f.x * f.x + f.y * f.y + f.z * f.z + f.w * f.w;
#pragma unroll
    for (int o = 16; o; o >>= 1) {
        s  += __shfl_xor_sync(0xffffffffu, s, o);
        sq += __shfl_xor_sync(0xffffffffu, sq, o);
    }
    __shared__ float ss[8], ssq[8];
    int w = threadIdx.x >> 5, l = threadIdx.x & 31;
    if (l == 0) { ss[w] = s; ssq[w] = sq; }
    __syncthreads();
    if (w == 0) {
        s  = (l < 8) ? ss[l]  : 0.f;
        sq = (l < 8) ? ssq[l] : 0.f;
#pragma unroll
        for (int o = 4; o; o >>= 1) {
            s  += __shfl_xor_sync(0xffffffffu, s, o);
            sq += __shfl_xor_sync(0xffffffffu, sq, o);
        }
        if (l == 0) { ss[0] = s; ssq[0] = sq; }
    }
    __syncthreads();
    float mu  = ss[0] * (1.f / DMODEL);
    float var = ssq[0] * (1.f / DMODEL) - mu * mu;
    float inv = rsqrtf(var + LN_EPS);
    float4 g = *(const float4*)(gamma + c0);
    float4 b = *(const float4*)(beta + c0);
    float o0 = (f.x - mu) * inv * g.x + b.x;
    float o1 = (f.y - mu) * inv * g.y + b.y;
    float o2 = (f.z - mu) * inv * g.z + b.z;
    float o3 = (f.w - mu) * inv * g.w + b.w;
    uint2 o;
    o.x = pack_bf2(o0, o1);
    o.y = pack_bf2(o2, o3);
    *(uint2*)&g_hb[(size_t)row * DMODEL + c0] = o;
}

// ---------------- weight fp32 -> bf16 -----------------------------------------
__global__ __launch_bounds__(256) void cvt_w_kernel(const float* __restrict__ Wq,
                                                    const float* __restrict__ Wk,
                                                    const float* __restrict__ Wv,
                                                    const float* __restrict__ Wo) {
    const float* src; bf16* dst;
    if (blockIdx.y == 0)      { src = Wq; dst = g_Wqb; }
    else if (blockIdx.y == 1) { src = Wk; dst = g_Wkb; }
    else if (blockIdx.y == 2) { src = Wv; dst = g_Wvb; }
    else                      { src = Wo; dst = g_Wob; }
    int i = (blockIdx.x * 256 + threadIdx.x) * 4;
    float4 f = *(const float4*)(src + i);
    uint2 o;
    o.x = pack_bf2(f.x, f.y);
    o.y = pack_bf2(f.z, f.w);
    *(uint2*)&dst[i] = o;
}

// ---------------- mask all-ones scan -----------------------------------------
__global__ void mask_init_kernel() { g_mask_allones = 1; }
__global__ void mask_scan_kernel(const int4* __restrict__ m4, int n4) {
    int ok = 1;
    for (int i = blockIdx.x * blockDim.x + threadIdx.x; i < n4;
         i += gridDim.x * blockDim.x) {
        int4 t = m4[i];
        ok &= (t.x != 0) & (t.y != 0) & (t.z != 0) & (t.w != 0);
    }
    if (!ok) atomicAnd(&g_mask_allones, 0);
}

// ---------------- shared GEMM mainloop (bf16 HMMA) -----------------------------
// C[128,128] tile of A[M,1024] @ W[N,1024]^T. 256 threads, 8 warps (2x4),
// warp tile 64x32, BK=32, cp.async double buffer, SW64-swizzled smem.
__device__ __forceinline__ void gemm_ml(const bf16* __restrict__ A,
                                        const bf16* __restrict__ W,
                                        int rowBase, int colBase,
                                        bf16 (*As)[128 * 32], bf16 (*Bs)[128 * 32],
                                        float acc[4][4][4]) {
    int tid = threadIdx.x, lane = tid & 31, warp = tid >> 5;
    int wm = warp >> 2, wn = warp & 3;
    int lrow = tid >> 2, lc = tid & 3;
    int j = lane >> 3, l7 = lane & 7;

#define GEMM_STAGE(st, kb)                                                         \
    {                                                                              \
        _Pragma("unroll")                                                          \
        for (int p = 0; p < 2; p++) {                                              \
            int row = lrow + p * 64;                                               \
            cp16(s2u(As[st]) + sw64(row, lc),                                      \
                 A + (size_t)(rowBase + row) * DMODEL + (kb) * 32 + lc * 8);       \
            cp16(s2u(Bs[st]) + sw64(row, lc),                                      \
                 W + (size_t)(colBase + row) * DMODEL + (kb) * 32 + lc * 8);       \
        }                                                                          \
    }

    GEMM_STAGE(0, 0);
    cp_commit(); cp_wait0();
    __syncthreads();

#pragma unroll 1
    for (int kb = 0; kb < 32; kb++) {
        int st = kb & 1;
        if (kb < 31) { GEMM_STAGE(st ^ 1, kb + 1); cp_commit(); }
        uint32_t ab = s2u(As[st]), bb_ = s2u(Bs[st]);
#pragma unroll
        for (int kt = 0; kt < 2; kt++) {
            uint32_t a[4][4];
#pragma unroll
            for (int mt = 0; mt < 4; mt++) {
                int row = wm * 64 + mt * 16 + ((j & 1) << 3) + l7;
                ldsm4(a[mt], ab + sw64(row, kt * 2 + (j >> 1)));
            }
            uint32_t b[4][2];
#pragma unroll
            for (int np = 0; np < 2; np++) {
                int row = wn * 32 + np * 16 + ((j >> 1) << 3) + l7;
                uint32_t r[4];
                ldsm4(r, bb_ + sw64(row, kt * 2 + (j & 1)));
                b[2 * np][0] = r[0]; b[2 * np][1] = r[1];
                b[2 * np + 1][0] = r[2]; b[2 * np + 1][1] = r[3];
            }
#pragma unroll
            for (int mt = 0; mt < 4; mt++)
#pragma unroll
                for (int nt = 0; nt < 4; nt++)
                    mma16816(acc[mt][nt], a[mt], b[nt]);
        }
        if (kb < 31) { cp_wait0(); __syncthreads(); }
    }
#undef GEMM_STAGE
}

// ---------------- QKV GEMM: bf16 out reordered to [B,H,S,hd] -------------------
__global__ __launch_bounds__(256) void gemm_qkv(const float* __restrict__ bq,
                                                const float* __restrict__ bk,
                                                const float* __restrict__ bv) {
    __shared__ bf16 As[2][128 * 32], Bs[2][128 * 32];
    const bf16* W; const float* bias; bf16* C;
    if (blockIdx.z == 0)      { W = g_Wqb; bias = bq; C = g_qb; }
    else if (blockIdx.z == 1) { W = g_Wkb; bias = bk; C = g_kb; }
    else                      { W = g_Wvb; bias = bv; C = g_vb; }

    float acc[4][4][4];
#pragma unroll
    for (int i = 0; i < 4; i++)
#pragma unroll
        for (int k = 0; k < 4; k++)
#pragma unroll
            for (int r = 0; r < 4; r++) acc[i][k][r] = 0.f;

    int rowBase = blockIdx.y * 128, colBase = blockIdx.x * 128;
    gemm_ml(g_hb, W, rowBase, colBase, As, Bs, acc);

    int lane = threadIdx.x & 31, warp = threadIdx.x >> 5;
    int wm = warp >> 2, wn = warp & 3;
    int r4 = lane >> 2, c2 = (lane & 3) * 2;
#pragma unroll
    for (int mt = 0; mt < 4; mt++)
#pragma unroll
        for (int nt = 0; nt < 4; nt++)
#pragma unroll
            for (int h = 0; h < 2; h++) {
                int m = rowBase + wm * 64 + mt * 16 + r4 + h * 8;
                int n = colBase + wn * 32 + nt * 8 + c2;
                float v0 = acc[mt][nt][h * 2 + 0] + bias[n];
                float v1 = acc[mt][nt][h * 2 + 1] + bias[n + 1];
                int bbi = m >> 11, s = m & 2047, hh = n >> 6, d = n & 63;
                *(uint32_t*)&C[(((size_t)(bbi * NHEAD + hh) * SEQ + s) << 6) + d] =
                    pack_bf2(v0, v1);
            }
}

// ---------------- out GEMM: fp32 out = attn @ Wo^T + bo + residual -------------
__global__ __launch_bounds__(256) void gemm_out(const float* __restrict__ bo,
                                                const float* __restrict__ resid,
                                                float* __restrict__ outp) {
    __shared__ bf16 As[2][128 * 32], Bs[2][128 * 32];
    float acc[4][4][4];
#pragma unroll
    for (int i = 0; i < 4; i++)
#pragma unroll
        for (int k = 0; k < 4; k++)
#pragma unroll
            for (int r = 0; r < 4; r++) acc[i][k][r] = 0.f;

    int rowBase = blockIdx.y * 128, colBase = blockIdx.x * 128;
    gemm_ml(g_attnb, g_Wob, rowBase, colBase, As, Bs, acc);

    int lane = threadIdx.x & 31, warp = threadIdx.x >> 5;
    int wm = warp >> 2, wn = warp & 3;
    int r4 = lane >> 2, c2 = (lane & 3) * 2;
#pragma unroll
    for (int mt = 0; mt < 4; mt++)
#pragma unroll
        for (int nt = 0; nt < 4; nt++)
#pragma unroll
            for (int h = 0; h < 2; h++) {
                int m = rowBase + wm * 64 + mt * 16 + r4 + h * 8;
                int n = colBase + wn * 32 + nt * 8 + c2;
                size_t idx = (size_t)m * DMODEL + n;
                float2 o;
                o.x = acc[mt][nt][h * 2 + 0] + bo[n] + resid[idx];
                o.y = acc[mt][nt][h * 2 + 1] + bo[n + 1] + resid[idx + 1];
                *(float2*)&outp[idx] = o;
            }
}

// ---------------- flash attention (bf16 HMMA, fp32 accum) ----------------------
// 128 threads = 4 warps; CTA = 64 q-rows; warp owns 16 rows. BN=64 per kv step.
// Q fragments live in registers for the whole loop; P repacked in registers.
__global__ __launch_bounds__(128) void attn_kernel(const int* __restrict__ mask) {
    __shared__ bf16 Qs[64 * 64];
    __shared__ bf16 Ks[2][64 * 64];
    __shared__ bf16 Vs[2][64 * 64];

    int tid = threadIdx.x, lane = tid & 31, warp = tid >> 5;
    int qt = blockIdx.x, hh = blockIdx.y, bb = blockIdx.z;
    size_t headOff = (size_t)(bb * NHEAD + hh) * SEQ * HDIM;
    const bf16* qp = g_qb + headOff + (size_t)qt * 64 * HDIM;
    const bf16* kp = g_kb + headOff;
    const bf16* vp = g_vb + headOff;

    int lrow = tid >> 3, lc8 = tid & 7;

#define KV_STAGE(st, ktile)                                                        \
    {                                                                              \
        const bf16* kt_p = kp + (size_t)(ktile) * 64 * HDIM;                       \
        const bf16* vt_p = vp + (size_t)(ktile) * 64 * HDIM;                       \
        _Pragma("unroll")                                                          \
        for (int p = 0; p < 4; p++) {                                              \
            int row = lrow + p * 16;                                               \
            cp16(s2u(Ks[st]) + sw128(row, lc8), kt_p + row * 64 + lc8 * 8);        \
            cp16(s2u(Vs[st]) + sw128(row, lc8), vt_p + row * 64 + lc8 * 8);        \
        }                                                                          \
    }

    // prologue: Q + stage 0
#pragma unroll
    for (int p = 0; p < 4; p++) {
        int row = lrow + p * 16;
        cp16(s2u(Qs) + sw128(row, lc8), qp + row * 64 + lc8 * 8);
    }
    KV_STAGE(0, 0);
    cp_commit(); cp_wait0();
    __syncthreads();

    int j = lane >> 3, l7 = lane & 7;
    uint32_t qf[4][4];
#pragma unroll
    for (int kt = 0; kt < 4; kt++) {
        int row = warp * 16 + ((j & 1) << 3) + l7;
        ldsm4(qf[kt], s2u(Qs) + sw128(row, kt * 2 + (j >> 1)));
    }

    float oacc[8][4];
#pragma unroll
    for (int nt = 0; nt < 8; nt++)
#pragma unroll
        for (int r = 0; r < 4; r++) oacc[nt][r] = 0.f;
    float m0 = -1e30f, m1 = -1e30f, l0 = 0.f, l1 = 0.f;
    bool use_mask = (g_mask_allones == 0);
    const float SC = 0.125f;   // 1/sqrt(64)

#pragma unroll 1
    for (int kt = 0; kt < SEQ / 64; kt++) {
        int st = kt & 1;
        if (kt < SEQ / 64 - 1) { KV_STAGE(st ^ 1, kt + 1); cp_commit(); }

        // --- scores = Q @ K^T ---
        float sacc[8][4];
#pragma unroll
        for (int nt = 0; nt < 8; nt++)
#pragma unroll
            for (int r = 0; r < 4; r++) sacc[nt][r] = 0.f;
        uint32_t kbse = s2u(Ks[st]);
#pragma unroll
        for (int kk = 0; kk < 4; kk++) {
            uint32_t bfrag[8][2];
#pragma unroll
            for (int np = 0; np < 4; np++) {
                int row = np * 16 + ((j >> 1) << 3) + l7;
                uint32_t r[4];
                ldsm4(r, kbse + sw128(row, kk * 2 + (j & 1)));
                bfrag[2 * np][0] = r[0]; bfrag[2 * np][1] = r[1];
                bfrag[2 * np + 1][0] = r[2]; bfrag[2 * np + 1][1] = r[3];
            }
#pragma unroll
            for (int nt = 0; nt < 8; nt++) mma16816(sacc[nt], qf[kk], bfrag[nt]);
        }

        if (use_mask) {
            int r0g = qt * 64 + warp * 16 + (lane >> 2);
            const int* mr0 = mask + ((size_t)bb * SEQ + r0g) * SEQ + kt * 64;
            const int* mr1 = mr0 + 8 * SEQ;
#pragma unroll
            for (int nt = 0; nt < 8; nt++) {
                int c0 = nt * 8 + (lane & 3) * 2;
                if (mr0[c0] == 0)     sacc[nt][0] = -1e30f;
                if (mr0[c0 + 1] == 0) sacc[nt][1] = -1e30f;
                if (mr1[c0] == 0)     sacc[nt][2] = -1e30f;
                if (mr1[c0 + 1] == 0) sacc[nt][3] = -1e30f;
            }
        }

        // --- register online softmax (rows r0 = lane/4, r1 = r0+8) ---
        float mx0 = -1e30f, mx1 = -1e30f;
#pragma unroll
        for (int nt = 0; nt < 8; nt++) {
            mx0 = fmaxf(mx0, fmaxf(sacc[nt][0], sacc[nt][1]));
            mx1 = fmaxf(mx1, fmaxf(sacc[nt][2], sacc[nt][3]));
        }
        mx0 = fmaxf(mx0, __shfl_xor_sync(0xffffffffu, mx0, 1));
        mx0 = fmaxf(mx0, __shfl_xor_sync(0xffffffffu, mx0, 2));
        mx1 = fmaxf(mx1, __shfl_xor_sync(0xffffffffu, mx1, 1));
        mx1 = fmaxf(mx1, __shfl_xor_sync(0xffffffffu, mx1, 2));
        float mn0 = fmaxf(m0, mx0 * SC), mn1 = fmaxf(m1, mx1 * SC);
        float cr0 = __expf(m0 - mn0), cr1 = __expf(m1 - mn1);
        float ls0 = 0.f, ls1 = 0.f;
#pragma unroll
        for (int nt = 0; nt < 8; nt++) {
            sacc[nt][0] = __expf(fmaf(sacc[nt][0], SC, -mn0)); ls0 += sacc[nt][0];
            sacc[nt][1] = __expf(fmaf(sacc[nt][1], SC, -mn0)); ls0 += sacc[nt][1];
            sacc[nt][2] = __expf(fmaf(sacc[nt][2], SC, -mn1)); ls1 += sacc[nt][2];
            sacc[nt][3] = __expf(fmaf(sacc[nt][3], SC, -mn1)); ls1 += sacc[nt][3];
        }
        ls0 += __shfl_xor_sync(0xffffffffu, ls0, 1);
        ls0 += __shfl_xor_sync(0xffffffffu, ls0, 2);
        ls1 += __shfl_xor_sync(0xffffffffu, ls1, 1);
        ls1 += __shfl_xor_sync(0xffffffffu, ls1, 2);
        l0 = l0 * cr0 + ls0; m0 = mn0;
        l1 = l1 * cr1 + ls1; m1 = mn1;
#pragma unroll
        for (int nt = 0; nt < 8; nt++) {
            oacc[nt][0] *= cr0; oacc[nt][1] *= cr0;
            oacc[nt][2] *= cr1; oacc[nt][3] *= cr1;
        }

        // --- PV: oacc += P @ V (P repacked register-only into A fragments) ---
        uint32_t vbse = s2u(Vs[st]);
#pragma unroll
        for (int k2 = 0; k2 < 4; k2++) {
            uint32_t pa[4] = {
                pack_bf2(sacc[2 * k2][0],     sacc[2 * k2][1]),
                pack_bf2(sacc[2 * k2][2],     sacc[2 * k2][3]),
                pack_bf2(sacc[2 * k2 + 1][0], sacc[2 * k2 + 1][1]),
                pack_bf2(sacc[2 * k2 + 1][2], sacc[2 * k2 + 1][3])
            };
#pragma unroll
            for (int np = 0; np < 4; np++) {
                int row = k2 * 16 + ((j & 1) << 3) + l7;
                uint32_t r[4];
                ldsm4t(r, vbse + sw128(row, np * 2 + (j >> 1)));
                uint32_t b0[2] = { r[0], r[1] };
                uint32_t b1[2] = { r[2], r[3] };
                mma16816(oacc[2 * np], pa, b0);
                mma16816(oacc[2 * np + 1], pa, b1);
            }
        }

        if (kt < SEQ / 64 - 1) { cp_wait0(); __syncthreads(); }
    }
#undef KV_STAGE

    // --- epilogue: normalize + write bf16 [B*S, D] ---
    float inv0 = 1.f / l0, inv1 = 1.f / l1;
    int r4 = lane >> 2, c2 = (lane & 3) * 2;
    int s0 = qt * 64 + warp * 16 + r4;
#pragma unroll
    for (int nt = 0; nt < 8; nt++) {
        int d = nt * 8 + c2;
        *(uint32_t*)&g_attnb[(size_t)(bb * SEQ + s0) * DMODEL + hh * 64 + d] =
            pack_bf2(oacc[nt][0] * inv0, oacc[nt][1] * inv0);
        *(uint32_t*)&g_attnb[(size_t)(bb * SEQ + s0 + 8) * DMODEL + hh * 64 + d] =
            pack_bf2(oacc[nt][2] * inv1, oacc[nt][3] * inv1);
    }
}

// ---------------- launcher ------------------------------------------------------
extern "C" void kernel_launch(void* const* d_in, const int* in_sizes, int n_in,
                              void* d_out, int out_size) {
    const float* x     = (const float*)d_in[0];
    const int*   mask  = (const int*)d_in[1];
    const float* Wq    = (const float*)d_in[2];
    const float* bq    = (const float*)d_in[3];
    const float* Wk    = (const float*)d_in[4];
    const float* bk    = (const float*)d_in[5];
    const float* Wv    = (const float*)d_in[6];
    const float* bv    = (const float*)d_in[7];
    const float* Wo    = (const float*)d_in[8];
    const float* bo    = (const float*)d_in[9];
    const float* gamma = (const float*)d_in[10];
    const float* beta  = (const float*)d_in[11];
    float* outp = (float*)d_out;

    ln_kernel<<<MROWS, 256>>>(x, gamma, beta);
    cvt_w_kernel<<<dim3(DMODEL * DMODEL / 1024, 4), 256>>>(Wq, Wk, Wv, Wo);

    mask_init_kernel<<<1, 1>>>();
    mask_scan_kernel<<<256, 256>>>((const int4*)mask, BATCH * SEQ * SEQ / 4);

    gemm_qkv<<<dim3(DMODEL / 128, MROWS / 128, 3), 256>>>(bq, bk, bv);

    attn_kernel<<<dim3(SEQ / 64, NHEAD, BATCH), 128>>>(mask);

    gemm_out<<<dim3(DMODEL / 128, MROWS / 128), 256>>>(bo, x, outp);
}

// round 6
// speedup vs baseline: 7.3728x; 1.0303x over previous
#include <cuda_runtime.h>
#include <cuda_bf16.h>
#include <cstdint>

#define BATCH 2
#define SEQ   2048
#define DMODEL 1024
#define NHEAD 16
#define HDIM  64
#define MROWS (BATCH * SEQ)
#define LN_EPS 1e-5f

typedef __nv_bfloat16 bf16;

// ---------------- device-global scratch (referenced ONLY from device code) ---
__device__ bf16 g_hb[(size_t)MROWS * DMODEL];     // LN output, bf16
__device__ bf16 g_Wqb[DMODEL * DMODEL];
__device__ bf16 g_Wkb[DMODEL * DMODEL];
__device__ bf16 g_Wvb[DMODEL * DMODEL];
__device__ bf16 g_Wob[DMODEL * DMODEL];
__device__ bf16 g_qb[(size_t)MROWS * DMODEL];     // [B,H,S,hd]
__device__ bf16 g_kb[(size_t)MROWS * DMODEL];
__device__ bf16 g_vb[(size_t)MROWS * DMODEL];
__device__ bf16 g_attnb[(size_t)MROWS * DMODEL];  // [B*S, D]
__device__ int  g_mask_allones;

// ---------------- PTX helpers -------------------------------------------------
__device__ __forceinline__ uint32_t s2u(const void* p) {
    return (uint32_t)__cvta_generic_to_shared(p);
}
__device__ __forceinline__ void cp16(uint32_t saddr, const void* g) {
    asm volatile("cp.async.cg.shared.global [%0], [%1], 16;\n" :: "r"(saddr), "l"(g));
}
__device__ __forceinline__ void cp_commit() { asm volatile("cp.async.commit_group;\n"); }
__device__ __forceinline__ void cp_wait0()  { asm volatile("cp.async.wait_group 0;\n"); }

__device__ __forceinline__ void ldsm4(uint32_t r[4], uint32_t addr) {
    asm volatile("ldmatrix.sync.aligned.m8n8.x4.shared.b16 {%0,%1,%2,%3}, [%4];\n"
                 : "=r"(r[0]), "=r"(r[1]), "=r"(r[2]), "=r"(r[3]) : "r"(addr));
}
__device__ __forceinline__ void ldsm4t(uint32_t r[4], uint32_t addr) {
    asm volatile("ldmatrix.sync.aligned.m8n8.x4.trans.shared.b16 {%0,%1,%2,%3}, [%4];\n"
                 : "=r"(r[0]), "=r"(r[1]), "=r"(r[2]), "=r"(r[3]) : "r"(addr));
}
__device__ __forceinline__ void mma16816(float c[4], const uint32_t a[4], const uint32_t b[2]) {
    asm volatile(
        "mma.sync.aligned.m16n8k16.row.col.f32.bf16.bf16.f32 "
        "{%0,%1,%2,%3}, {%4,%5,%6,%7}, {%8,%9}, {%0,%1,%2,%3};\n"
        : "+f"(c[0]), "+f"(c[1]), "+f"(c[2]), "+f"(c[3])
        : "r"(a[0]), "r"(a[1]), "r"(a[2]), "r"(a[3]), "r"(b[0]), "r"(b[1]));
}
__device__ __forceinline__ uint32_t pack_bf2(float lo, float hi) {
    __nv_bfloat162 h = __floats2bfloat162_rn(lo, hi);
    return *reinterpret_cast<uint32_t*>(&h);
}
// swizzles: byte offset within a tile whose rows are 64B / 128B wide
__device__ __forceinline__ int sw64(int row, int c16)  { return (row << 6) + ((c16 ^ ((row >> 1) & 3)) << 4); }
__device__ __forceinline__ int sw128(int row, int c16) { return (row << 7) + ((c16 ^ (row & 7)) << 4); }

// ---------------- layernorm -> bf16 ------------------------------------------
__global__ __launch_bounds__(256) void ln_kernel(const float* __restrict__ x,
                                                 const float* __restrict__ gamma,
                                                 const float* __restrict__ beta) {
    int row = blockIdx.x;
    const float* xr = x + (size_t)row * DMODEL;
    int c0 = threadIdx.x * 4;
    float4 f = *(const float4*)(xr + c0);
    float s  = f.x + f.y + f.z + f.w;
    float sq = f.x * f.x + f.y * f.y + f.z * f.z + f.w * f.w;
#pragma unroll
    for (int o = 16; o; o >>= 1) {
        s  += __shfl_xor_sync(0xffffffffu, s, o);
        sq += __shfl_xor_sync(0xffffffffu, sq, o);
    }
    __shared__ float ss[8], ssq[8];
    int w = threadIdx.x >> 5, l = threadIdx.x & 31;
    if (l == 0) { ss[w] = s; ssq[w] = sq; }
    __syncthreads();
    if (w == 0) {
        s  = (l < 8) ? ss[l]  : 0.f;
        sq = (l < 8) ? ssq[l] : 0.f;
#pragma unroll
        for (int o = 4; o; o >>= 1) {
            s  += __shfl_xor_sync(0xffffffffu, s, o);
            sq += __shfl_xor_sync(0xffffffffu, sq, o);
        }
        if (l == 0) { ss[0] = s; ssq[0] = sq; }
    }
    __syncthreads();
    float mu  = ss[0] * (1.f / DMODEL);
    float var = ssq[0] * (1.f / DMODEL) - mu * mu;
    float inv = rsqrtf(var + LN_EPS);
    float4 g = *(const float4*)(gamma + c0);
    float4 b = *(const float4*)(beta + c0);
    float o0 = (f.x - mu) * inv * g.x + b.x;
    float o1 = (f.y - mu) * inv * g.y + b.y;
    float o2 = (f.z - mu) * inv * g.z + b.z;
    float o3 = (f.w - mu) * inv * g.w + b.w;
    uint2 o;
    o.x = pack_bf2(o0, o1);
    o.y = pack_bf2(o2, o3);
    *(uint2*)&g_hb[(size_t)row * DMODEL + c0] = o;
}

// ---------------- weight fp32 -> bf16 (+ mask flag init) -----------------------
__global__ __launch_bounds__(256) void cvt_w_kernel(const float* __restrict__ Wq,
                                                    const float* __restrict__ Wk,
                                                    const float* __restrict__ Wv,
                                                    const float* __restrict__ Wo) {
    if (blockIdx.x == 0 && blockIdx.y == 0 && threadIdx.x == 0) g_mask_allones = 1;
    const float* src; bf16* dst;
    if (blockIdx.y == 0)      { src = Wq; dst = g_Wqb; }
    else if (blockIdx.y == 1) { src = Wk; dst = g_Wkb; }
    else if (blockIdx.y == 2) { src = Wv; dst = g_Wvb; }
    else                      { src = Wo; dst = g_Wob; }
    int i = (blockIdx.x * 256 + threadIdx.x) * 4;
    float4 f = *(const float4*)(src + i);
    uint2 o;
    o.x = pack_bf2(f.x, f.y);
    o.y = pack_bf2(f.z, f.w);
    *(uint2*)&dst[i] = o;
}

// ---------------- mask all-ones scan (8 independent loads / thread) -----------
// n4 = 2M int4; grid 1024 x 256 x 8 = 2M exactly.
__global__ __launch_bounds__(256) void mask_scan_kernel(const int4* __restrict__ m4) {
    int base = blockIdx.x * (256 * 8) + threadIdx.x;
    int4 t[8];
#pragma unroll
    for (int u = 0; u < 8; u++) t[u] = m4[base + u * 256];
    int ok = 1;
#pragma unroll
    for (int u = 0; u < 8; u++)
        ok &= (t[u].x != 0) & (t[u].y != 0) & (t[u].z != 0) & (t[u].w != 0);
    if (!ok) atomicAnd(&g_mask_allones, 0);
}

// ---------------- shared GEMM mainloop (bf16 HMMA) -----------------------------
__device__ __forceinline__ void gemm_ml(const bf16* __restrict__ A,
                                        const bf16* __restrict__ W,
                                        int rowBase, int colBase,
                                        bf16 (*As)[128 * 32], bf16 (*Bs)[128 * 32],
                                        float acc[4][4][4]) {
    int tid = threadIdx.x, lane = tid & 31, warp = tid >> 5;
    int wm = warp >> 2, wn = warp & 3;
    int lrow = tid >> 2, lc = tid & 3;
    int j = lane >> 3, l7 = lane & 7;

#define GEMM_STAGE(st, kb)                                                         \
    {                                                                              \
        _Pragma("unroll")                                                          \
        for (int p = 0; p < 2; p++) {                                              \
            int row = lrow + p * 64;                                               \
            cp16(s2u(As[st]) + sw64(row, lc),                                      \
                 A + (size_t)(rowBase + row) * DMODEL + (kb) * 32 + lc * 8);       \
            cp16(s2u(Bs[st]) + sw64(row, lc),                                      \
                 W + (size_t)(colBase + row) * DMODEL + (kb) * 32 + lc * 8);       \
        }                                                                          \
    }

    GEMM_STAGE(0, 0);
    cp_commit(); cp_wait0();
    __syncthreads();

#pragma unroll 1
    for (int kb = 0; kb < 32; kb++) {
        int st = kb & 1;
        if (kb < 31) { GEMM_STAGE(st ^ 1, kb + 1); cp_commit(); }
        uint32_t ab = s2u(As[st]), bb_ = s2u(Bs[st]);
#pragma unroll
        for (int kt = 0; kt < 2; kt++) {
            uint32_t a[4][4];
#pragma unroll
            for (int mt = 0; mt < 4; mt++) {
                int row = wm * 64 + mt * 16 + ((j & 1) << 3) + l7;
                ldsm4(a[mt], ab + sw64(row, kt * 2 + (j >> 1)));
            }
            uint32_t b[4][2];
#pragma unroll
            for (int np = 0; np < 2; np++) {
                int row = wn * 32 + np * 16 + ((j >> 1) << 3) + l7;
                uint32_t r[4];
                ldsm4(r, bb_ + sw64(row, kt * 2 + (j & 1)));
                b[2 * np][0] = r[0]; b[2 * np][1] = r[1];
                b[2 * np + 1][0] = r[2]; b[2 * np + 1][1] = r[3];
            }
#pragma unroll
            for (int mt = 0; mt < 4; mt++)
#pragma unroll
                for (int nt = 0; nt < 4; nt++)
                    mma16816(acc[mt][nt], a[mt], b[nt]);
        }
        if (kb < 31) { cp_wait0(); __syncthreads(); }
    }
#undef GEMM_STAGE
}

// ---------------- QKV GEMM: bf16 out reordered to [B,H,S,hd] -------------------
__global__ __launch_bounds__(256) void gemm_qkv(const float* __restrict__ bq,
                                                const float* __restrict__ bk,
                                                const float* __restrict__ bv) {
    __shared__ bf16 As[2][128 * 32], Bs[2][128 * 32];
    const bf16* W; const float* bias; bf16* C;
    if (blockIdx.z == 0)      { W = g_Wqb; bias = bq; C = g_qb; }
    else if (blockIdx.z == 1) { W = g_Wkb; bias = bk; C = g_kb; }
    else                      { W = g_Wvb; bias = bv; C = g_vb; }

    float acc[4][4][4];
#pragma unroll
    for (int i = 0; i < 4; i++)
#pragma unroll
        for (int k = 0; k < 4; k++)
#pragma unroll
            for (int r = 0; r < 4; r++) acc[i][k][r] = 0.f;

    int rowBase = blockIdx.y * 128, colBase = blockIdx.x * 128;
    gemm_ml(g_hb, W, rowBase, colBase, As, Bs, acc);

    int lane = threadIdx.x & 31, warp = threadIdx.x >> 5;
    int wm = warp >> 2, wn = warp & 3;
    int r4 = lane >> 2, c2 = (lane & 3) * 2;
#pragma unroll
    for (int mt = 0; mt < 4; mt++)
#pragma unroll
        for (int nt = 0; nt < 4; nt++)
#pragma unroll
            for (int h = 0; h < 2; h++) {
                int m = rowBase + wm * 64 + mt * 16 + r4 + h * 8;
                int n = colBase + wn * 32 + nt * 8 + c2;
                float v0 = acc[mt][nt][h * 2 + 0] + bias[n];
                float v1 = acc[mt][nt][h * 2 + 1] + bias[n + 1];
                int bbi = m >> 11, s = m & 2047, hh = n >> 6, d = n & 63;
                *(uint32_t*)&C[(((size_t)(bbi * NHEAD + hh) * SEQ + s) << 6) + d] =
                    pack_bf2(v0, v1);
            }
}

// ---------------- out GEMM: fp32 out = attn @ Wo^T + bo + residual -------------
__global__ __launch_bounds__(256) void gemm_out(const float* __restrict__ bo,
                                                const float* __restrict__ resid,
                                                float* __restrict__ outp) {
    __shared__ bf16 As[2][128 * 32], Bs[2][128 * 32];
    float acc[4][4][4];
#pragma unroll
    for (int i = 0; i < 4; i++)
#pragma unroll
        for (int k = 0; k < 4; k++)
#pragma unroll
            for (int r = 0; r < 4; r++) acc[i][k][r] = 0.f;

    int rowBase = blockIdx.y * 128, colBase = blockIdx.x * 128;
    gemm_ml(g_attnb, g_Wob, rowBase, colBase, As, Bs, acc);

    int lane = threadIdx.x & 31, warp = threadIdx.x >> 5;
    int wm = warp >> 2, wn = warp & 3;
    int r4 = lane >> 2, c2 = (lane & 3) * 2;
#pragma unroll
    for (int mt = 0; mt < 4; mt++)
#pragma unroll
        for (int nt = 0; nt < 4; nt++)
#pragma unroll
            for (int h = 0; h < 2; h++) {
                int m = rowBase + wm * 64 + mt * 16 + r4 + h * 8;
                int n = colBase + wn * 32 + nt * 8 + c2;
                size_t idx = (size_t)m * DMODEL + n;
                float2 o;
                o.x = acc[mt][nt][h * 2 + 0] + bo[n] + resid[idx];
                o.y = acc[mt][nt][h * 2 + 1] + bo[n + 1] + resid[idx + 1];
                *(float2*)&outp[idx] = o;
            }
}

// ---------------- flash attention (bf16 HMMA, fp32 accum, BN=128) --------------
// 128 threads = 4 warps; CTA = 64 q-rows, warp owns 16. kv tile = 128 rows per
// softmax pass (halves softmax/rescale/sync overhead vs BN=64).
// Dynamic smem: Qs 8KB + Ks[2] 32KB + Vs[2] 32KB = 72KB.
#define ATTN_SMEM (64 * 64 * 2 + 4 * 128 * 64 * 2)
__global__ __launch_bounds__(128) void attn_kernel(const int* __restrict__ mask) {
    extern __shared__ bf16 smem_a[];
    bf16* Qs = smem_a;                       // 64 x 64
    bf16* Ks[2] = { Qs + 64 * 64,  Qs + 64 * 64 + 128 * 64 };
    bf16* Vs[2] = { Qs + 64 * 64 + 2 * 128 * 64,
                    Qs + 64 * 64 + 3 * 128 * 64 };

    int tid = threadIdx.x, lane = tid & 31, warp = tid >> 5;
    int qt = blockIdx.x, hh = blockIdx.y, bb = blockIdx.z;
    size_t headOff = (size_t)(bb * NHEAD + hh) * SEQ * HDIM;
    const bf16* qp = g_qb + headOff + (size_t)qt * 64 * HDIM;
    const bf16* kp = g_kb + headOff;
    const bf16* vp = g_vb + headOff;

    int lrow = tid >> 3, lc8 = tid & 7;

#define KV_STAGE(st, ktile)                                                        \
    {                                                                              \
        const bf16* kt_p = kp + (size_t)(ktile) * 128 * HDIM;                      \
        const bf16* vt_p = vp + (size_t)(ktile) * 128 * HDIM;                      \
        _Pragma("unroll")                                                          \
        for (int p = 0; p < 8; p++) {                                              \
            int row = lrow + p * 16;                                               \
            cp16(s2u(Ks[st]) + sw128(row, lc8), kt_p + row * 64 + lc8 * 8);        \
            cp16(s2u(Vs[st]) + sw128(row, lc8), vt_p + row * 64 + lc8 * 8);        \
        }                                                                          \
    }

    // prologue: Q + stage 0
#pragma unroll
    for (int p = 0; p < 4; p++) {
        int row = lrow + p * 16;
        cp16(s2u(Qs) + sw128(row, lc8), qp + row * 64 + lc8 * 8);
    }
    KV_STAGE(0, 0);
    cp_commit(); cp_wait0();
    __syncthreads();

    int j = lane >> 3, l7 = lane & 7;
    uint32_t qf[4][4];
#pragma unroll
    for (int kt = 0; kt < 4; kt++) {
        int row = warp * 16 + ((j & 1) << 3) + l7;
        ldsm4(qf[kt], s2u(Qs) + sw128(row, kt * 2 + (j >> 1)));
    }

    float oacc[8][4];
#pragma unroll
    for (int nt = 0; nt < 8; nt++)
#pragma unroll
        for (int r = 0; r < 4; r++) oacc[nt][r] = 0.f;
    float m0 = -1e30f, m1 = -1e30f, l0 = 0.f, l1 = 0.f;
    bool use_mask = (g_mask_allones == 0);
    const float SC = 0.125f;   // 1/sqrt(64)

#pragma unroll 1
    for (int kt = 0; kt < SEQ / 128; kt++) {
        int st = kt & 1;
        if (kt < SEQ / 128 - 1) { KV_STAGE(st ^ 1, kt + 1); cp_commit(); }

        // --- scores = Q @ K^T over 128 kv cols ---
        float sacc[16][4];
#pragma unroll
        for (int nt = 0; nt < 16; nt++)
#pragma unroll
            for (int r = 0; r < 4; r++) sacc[nt][r] = 0.f;
        uint32_t kbse = s2u(Ks[st]);
#pragma unroll
        for (int kk = 0; kk < 4; kk++) {
#pragma unroll
            for (int np = 0; np < 8; np++) {
                int row = np * 16 + ((j >> 1) << 3) + l7;
                uint32_t r[4];
                ldsm4(r, kbse + sw128(row, kk * 2 + (j & 1)));
                uint32_t b0[2] = { r[0], r[1] };
                uint32_t b1[2] = { r[2], r[3] };
                mma16816(sacc[2 * np], qf[kk], b0);
                mma16816(sacc[2 * np + 1], qf[kk], b1);
            }
        }

        if (use_mask) {
            int r0g = qt * 64 + warp * 16 + (lane >> 2);
            const int* mr0 = mask + ((size_t)bb * SEQ + r0g) * SEQ + kt * 128;
            const int* mr1 = mr0 + 8 * SEQ;
#pragma unroll
            for (int nt = 0; nt < 16; nt++) {
                int c0 = nt * 8 + (lane & 3) * 2;
                if (mr0[c0] == 0)     sacc[nt][0] = -1e30f;
                if (mr0[c0 + 1] == 0) sacc[nt][1] = -1e30f;
                if (mr1[c0] == 0)     sacc[nt][2] = -1e30f;
                if (mr1[c0 + 1] == 0) sacc[nt][3] = -1e30f;
            }
        }

        // --- register online softmax (rows r0 = lane/4, r1 = r0+8) ---
        float mx0 = -1e30f, mx1 = -1e30f;
#pragma unroll
        for (int nt = 0; nt < 16; nt++) {
            mx0 = fmaxf(mx0, fmaxf(sacc[nt][0], sacc[nt][1]));
            mx1 = fmaxf(mx1, fmaxf(sacc[nt][2], sacc[nt][3]));
        }
        mx0 = fmaxf(mx0, __shfl_xor_sync(0xffffffffu, mx0, 1));
        mx0 = fmaxf(mx0, __shfl_xor_sync(0xffffffffu, mx0, 2));
        mx1 = fmaxf(mx1, __shfl_xor_sync(0xffffffffu, mx1, 1));
        mx1 = fmaxf(mx1, __shfl_xor_sync(0xffffffffu, mx1, 2));
        float mn0 = fmaxf(m0, mx0 * SC), mn1 = fmaxf(m1, mx1 * SC);
        float cr0 = __expf(m0 - mn0), cr1 = __expf(m1 - mn1);
        float ls0 = 0.f, ls1 = 0.f;
#pragma unroll
        for (int nt = 0; nt < 16; nt++) {
            sacc[nt][0] = __expf(fmaf(sacc[nt][0], SC, -mn0)); ls0 += sacc[nt][0];
            sacc[nt][1] = __expf(fmaf(sacc[nt][1], SC, -mn0)); ls0 += sacc[nt][1];
            sacc[nt][2] = __expf(fmaf(sacc[nt][2], SC, -mn1)); ls1 += sacc[nt][2];
            sacc[nt][3] = __expf(fmaf(sacc[nt][3], SC, -mn1)); ls1 += sacc[nt][3];
        }
        ls0 += __shfl_xor_sync(0xffffffffu, ls0, 1);
        ls0 += __shfl_xor_sync(0xffffffffu, ls0, 2);
        ls1 += __shfl_xor_sync(0xffffffffu, ls1, 1);
        ls1 += __shfl_xor_sync(0xffffffffu, ls1, 2);
        l0 = l0 * cr0 + ls0; m0 = mn0;
        l1 = l1 * cr1 + ls1; m1 = mn1;
#pragma unroll
        for (int nt = 0; nt < 8; nt++) {
            oacc[nt][0] *= cr0; oacc[nt][1] *= cr0;
            oacc[nt][2] *= cr1; oacc[nt][3] *= cr1;
        }

        // --- PV: oacc += P @ V over 128 kv rows ---
        uint32_t vbse = s2u(Vs[st]);
#pragma unroll
        for (int k2 = 0; k2 < 8; k2++) {
            uint32_t pa[4] = {
                pack_bf2(sacc[2 * k2][0],     sacc[2 * k2][1]),
                pack_bf2(sacc[2 * k2][2],     sacc[2 * k2][3]),
                pack_bf2(sacc[2 * k2 + 1][0], sacc[2 * k2 + 1][1]),
                pack_bf2(sacc[2 * k2 + 1][2], sacc[2 * k2 + 1][3])
            };
#pragma unroll
            for (int np = 0; np < 4; np++) {
                int row = k2 * 16 + ((j & 1) << 3) + l7;
                uint32_t r[4];
                ldsm4t(r, vbse + sw128(row, np * 2 + (j >> 1)));
                uint32_t b0[2] = { r[0], r[1] };
                uint32_t b1[2] = { r[2], r[3] };
                mma16816(oacc[2 * np], pa, b0);
                mma16816(oacc[2 * np + 1], pa, b1);
            }
        }

        if (kt < SEQ / 128 - 1) { cp_wait0(); __syncthreads(); }
    }
#undef KV_STAGE

    // --- epilogue: normalize + write bf16 [B*S, D] ---
    float inv0 = 1.f / l0, inv1 = 1.f / l1;
    int r4 = lane >> 2, c2 = (lane & 3) * 2;
    int s0 = qt * 64 + warp * 16 + r4;
#pragma unroll
    for (int nt = 0; nt < 8; nt++) {
        int d = nt * 8 + c2;
        *(uint32_t*)&g_attnb[(size_t)(bb * SEQ + s0) * DMODEL + hh * 64 + d] =
            pack_bf2(oacc[nt][0] * inv0, oacc[nt][1] * inv0);
        *(uint32_t*)&g_attnb[(size_t)(bb * SEQ + s0 + 8) * DMODEL + hh * 64 + d] =
            pack_bf2(oacc[nt][2] * inv1, oacc[nt][3] * inv1);
    }
}

// ---------------- launcher ------------------------------------------------------
extern "C" void kernel_launch(void* const* d_in, const int* in_sizes, int n_in,
                              void* d_out, int out_size) {
    const float* x     = (const float*)d_in[0];
    const int*   mask  = (const int*)d_in[1];
    const float* bq    = (const float*)d_in[3];
    const float* bk    = (const float*)d_in[5];
    const float* bv    = (const float*)d_in[7];
    const float* bo    = (const float*)d_in[9];
    const float* gamma = (const float*)d_in[10];
    const float* beta  = (const float*)d_in[11];
    float* outp = (float*)d_out;

    cudaFuncSetAttribute(attn_kernel, cudaFuncAttributeMaxDynamicSharedMemorySize,
                         ATTN_SMEM);

    ln_kernel<<<MROWS, 256>>>(x, gamma, beta);
    cvt_w_kernel<<<dim3(DMODEL * DMODEL / 1024, 4), 256>>>(
        (const float*)d_in[2], (const float*)d_in[4],
        (const float*)d_in[6], (const float*)d_in[8]);

    mask_scan_kernel<<<BATCH * SEQ * SEQ / 4 / (256 * 8), 256>>>((const int4*)mask);

    gemm_qkv<<<dim3(DMODEL / 128, MROWS / 128, 3), 256>>>(bq, bk, bv);

    attn_kernel<<<dim3(SEQ / 64, NHEAD, BATCH), 128, ATTN_SMEM>>>(mask);

    gemm_out<<<dim3(DMODEL / 128, MROWS / 128), 256>>>(bo, x, outp);
}